// round 12
// baseline (speedup 1.0000x reference)
#include <cuda_runtime.h>
#include <cuda_fp16.h>
#include <math.h>
#include <stdint.h>

#define B_ 1024
#define D_ 1024
#define H_ 4096
#define C_ 5120
#define LN_EPS 1e-3f
#define KSLICE_D 4

// ---------------- scratch (device globals: allocation-free) ----------------
__device__ __align__(1024) __half g_a1[B_ * C_];
__device__ __align__(1024) __half g_a2[B_ * C_];
__device__ __align__(1024) __half g_a3[B_ * H_];
__device__ __align__(1024) __half g_wu[(long)H_ * C_];
__device__ __align__(1024) __half g_wr[(long)H_ * C_];
__device__ __align__(1024) __half g_wg[(long)H_ * C_];
__device__ __align__(1024) __half g_wp[(long)H_ * C_];
__device__ __align__(1024) __half g_wd[(long)D_ * H_];
__device__ float g_u [B_ * H_];
__device__ float g_g [B_ * H_];
__device__ float g_up[B_ * H_];
__device__ float g_nh[B_ * H_];
__device__ float g_do[KSLICE_D * B_ * D_];

// ---------------- helpers ----------------
__device__ __forceinline__ uint32_t smem_u32(const void* p) {
    uint32_t a;
    asm("{ .reg .u64 t; cvta.to.shared.u64 t, %1; cvt.u32.u64 %0, t; }" : "=r"(a) : "l"(p));
    return a;
}
__device__ __forceinline__ void cp16(uint32_t dst, const void* src) {
    asm volatile("cp.async.cg.shared.global [%0], [%1], 16;" :: "r"(dst), "l"(src) : "memory");
}
__device__ __forceinline__ void ldsm_x4(uint32_t* r, uint32_t addr) {
    asm volatile("ldmatrix.sync.aligned.m8n8.x4.shared.b16 {%0,%1,%2,%3}, [%4];"
                 : "=r"(r[0]), "=r"(r[1]), "=r"(r[2]), "=r"(r[3]) : "r"(addr));
}
__device__ __forceinline__ void mma_f32(float* c, const uint32_t* a, uint32_t b0, uint32_t b1) {
    asm volatile(
        "mma.sync.aligned.m16n8k16.row.col.f32.f16.f16.f32 "
        "{%0,%1,%2,%3}, {%4,%5,%6,%7}, {%8,%9}, {%0,%1,%2,%3};"
        : "+f"(c[0]), "+f"(c[1]), "+f"(c[2]), "+f"(c[3])
        : "r"(a[0]), "r"(a[1]), "r"(a[2]), "r"(a[3]), "r"(b0), "r"(b1));
}
__device__ __forceinline__ float sigm(float x) { return 1.0f / (1.0f + expf(-x)); }

// swizzled offset inside a [rows][32 fp16] tile (64B rows, 16B chunks)
__device__ __forceinline__ uint32_t sw_off(int row, int cb) {
    return (uint32_t)row * 64u + (uint32_t)((cb ^ ((row >> 1) & 3)) << 4);
}

// ---------------- single-term fp16 HMMA GEMM, 128x256 CTA tile, 64x64 warp tiles ----------------
#define KT 32
#define STG 3
#define NT 256
#define STAGE_BYTES 24576u   // A(0): 128x32 = 8KB; B(8192): 256x32 = 16KB

template<int MODE>
__global__ void __launch_bounds__(256, 1) gemm_hmma(
    const __half* __restrict__ A, int ldA,
    const __half* __restrict__ B0, const __half* __restrict__ B1, int ldB,
    const float* __restrict__ bias0, const float* __restrict__ bias1,
    const float* __restrict__ hmul,
    float* __restrict__ fout0, float* __restrict__ fout1,
    __half* __restrict__ oba,
    int K, int nhalf, int kslices)
{
    extern __shared__ __align__(1024) char smraw[];
    const uint32_t sb = smem_u32(smraw);

    const int tid = threadIdx.x, lane = tid & 31, wid = tid >> 5;
    const int wm = (wid >> 2) * 64;   // warp M offset (0/64)
    const int wn = (wid & 3) * 64;    // warp N offset (0/64/128/192)
    const int nt = blockIdx.x, mt = blockIdx.y;
    const bool second = nt >= nhalf;
    const int ntin = second ? nt - nhalf : nt;
    const __half* Bp = second ? B1 : B0;
    const float* bias = second ? bias1 : bias0;

    const int m0 = mt * 128, n0 = ntin * NT;
    const int Ks = K / kslices;
    const int kbeg = blockIdx.z * Ks;
    const int S = Ks / KT;

    // ---- stage loader: A 128x32 (512 cp16), B 256x32 (1024 cp16); 6 cp16/thread ----
    const int lrA  = tid >> 1;
    const int lcbA = (tid & 1) * 2;
    auto load_stage = [&](int slot, int kk) {
        const uint32_t tb = sb + (uint32_t)slot * STAGE_BYTES;
        const size_t arow = (size_t)(m0 + lrA) * ldA + kk;
#pragma unroll
        for (int c = 0; c < 2; c++) {
            const int cb = lcbA + c;
            cp16(tb + sw_off(lrA, cb), A + arow + cb * 8);
        }
        const size_t brow = (size_t)(n0 + tid) * ldB + kk;
#pragma unroll
        for (int cb = 0; cb < 4; cb++)
            cp16(tb + 8192 + sw_off(tid, cb), Bp + brow + cb * 8);
    };

    // precomputed ldsm offsets (s=0 chunk; s=1 toggles ^32)
    const int lb = (lane >> 4) & 1;
    uint32_t offA[4], offB[4];
#pragma unroll
    for (int i = 0; i < 4; i++) offA[i] = sw_off(wm + i * 16 + (lane & 15), lb);
#pragma unroll
    for (int jp = 0; jp < 4; jp++) offB[jp] = sw_off(wn + jp * 16 + (lane & 15), lb);

    // prologue
#pragma unroll
    for (int s = 0; s < STG - 1; s++) {
        if (s < S) load_stage(s, kbeg + s * KT);
        asm volatile("cp.async.commit_group;" ::: "memory");
    }

    float acc[4][8][4];
#pragma unroll
    for (int i = 0; i < 4; i++)
#pragma unroll
        for (int j = 0; j < 8; j++)
#pragma unroll
            for (int e = 0; e < 4; e++) acc[i][j][e] = 0.f;

    for (int ks = 0; ks < S; ks++) {
        asm volatile("cp.async.wait_group 1;" ::: "memory");
        __syncthreads();
        if (ks + STG - 1 < S) load_stage((ks + STG - 1) % STG, kbeg + (ks + STG - 1) * KT);
        asm volatile("cp.async.commit_group;" ::: "memory");

        const uint32_t base = sb + (uint32_t)(ks % STG) * STAGE_BYTES;
#pragma unroll
        for (int s = 0; s < 2; s++) {
            const uint32_t sx = (uint32_t)(s << 5);
            uint32_t a[4][4], b[4][4];
#pragma unroll
            for (int i = 0; i < 4; i++)   ldsm_x4(a[i], base + (offA[i] ^ sx));
#pragma unroll
            for (int jp = 0; jp < 4; jp++) ldsm_x4(b[jp], base + 8192 + (offB[jp] ^ sx));
#pragma unroll
            for (int i = 0; i < 4; i++)
#pragma unroll
                for (int j = 0; j < 8; j++)
                    mma_f32(acc[i][j], a[i], b[j >> 1][j & 1], b[j >> 1][2 | (j & 1)]);
        }
    }

    // ---- epilogue ----
#pragma unroll
    for (int i = 0; i < 4; i++) {
#pragma unroll
        for (int j = 0; j < 8; j++) {
            const int r0 = m0 + wm + i * 16 + (lane >> 2);
            const int gc = ntin * NT + wn + j * 8 + 2 * (lane & 3);
#pragma unroll
            for (int half = 0; half < 2; half++) {
                const int row = r0 + half * 8;
                const float v0r = acc[i][j][half * 2];
                const float v1r = acc[i][j][half * 2 + 1];
                if (MODE == 0) {
                    const float v0 = v0r + bias[gc], v1 = v1r + bias[gc + 1];
                    if (!second) {
                        fout0[(long)row * H_ + gc]     = sigm(v0);
                        fout0[(long)row * H_ + gc + 1] = sigm(v1);
                    } else {
                        const float rh0 = sigm(v0) * hmul[(long)row * H_ + gc];
                        const float rh1 = sigm(v1) * hmul[(long)row * H_ + gc + 1];
                        oba[(long)row * C_ + D_ + gc]     = __float2half_rn(rh0);
                        oba[(long)row * C_ + D_ + gc + 1] = __float2half_rn(rh1);
                    }
                } else if (MODE == 1) {
                    float* dst = second ? fout1 : fout0;
                    dst[(long)row * H_ + gc]     = v0r + bias[gc];
                    dst[(long)row * H_ + gc + 1] = v1r + bias[gc + 1];
                } else {
                    float* dst = fout0 + (size_t)blockIdx.z * B_ * D_;
                    dst[(long)row * D_ + gc]     = v0r;
                    dst[(long)row * D_ + gc + 1] = v1r;
                }
            }
        }
    }
}

// ---------------- conversion kernels ----------------
__global__ void conv_a1(const float* __restrict__ x, const float* __restrict__ h,
                        __half* __restrict__ a1, __half* __restrict__ a2)
{
    const long i4 = (long)blockIdx.x * blockDim.x + threadIdx.x;
    if (i4 >= (long)B_ * C_ / 4) return;
    const int row = (int)(i4 / (C_ / 4));
    const int c = (int)(i4 % (C_ / 4)) * 4;
    float4 f;
    if (c < D_) f = *(const float4*)(x + (long)row * D_ + c);
    else        f = *(const float4*)(h + (long)row * H_ + (c - D_));
    __half2 hv0 = __halves2half2(__float2half_rn(f.x), __float2half_rn(f.y));
    __half2 hv1 = __halves2half2(__float2half_rn(f.z), __float2half_rn(f.w));
    const long o = (long)row * C_ + c;
    *(uint2*)(a1 + o) = make_uint2(*(uint32_t*)&hv0, *(uint32_t*)&hv1);
    if (c < D_)
        *(uint2*)(a2 + o) = make_uint2(*(uint32_t*)&hv0, *(uint32_t*)&hv1);
}

// batched transpose + round to fp16 for the 4 big weights
__global__ void tconv4(const float* __restrict__ s0, const float* __restrict__ s1,
                       const float* __restrict__ s2, const float* __restrict__ s3,
                       __half* __restrict__ d0, __half* __restrict__ d1,
                       __half* __restrict__ d2, __half* __restrict__ d3)
{
    const int z = blockIdx.z;
    const float* src = z == 0 ? s0 : z == 1 ? s1 : z == 2 ? s2 : s3;
    __half* dh = z == 0 ? d0 : z == 1 ? d1 : z == 2 ? d2 : d3;
    const int K = C_, N = H_;

    __shared__ float t[64][33];
    const int kt = blockIdx.y * 64, nb = blockIdx.x * 32;
    const int tid = threadIdx.x;
    {
        const int c4 = (tid & 7) * 4, r0 = tid >> 3;
#pragma unroll
        for (int p = 0; p < 2; p++) {
            const int r = r0 + p * 32;
            const float4 f = *(const float4*)(src + (size_t)(kt + r) * N + nb + c4);
            t[r][c4] = f.x; t[r][c4 + 1] = f.y; t[r][c4 + 2] = f.z; t[r][c4 + 3] = f.w;
        }
    }
    __syncthreads();
    const int n  = tid >> 3;
    const int k8 = (tid & 7) * 8;
    __half2 hv[4];
#pragma unroll
    for (int i = 0; i < 4; i++)
        hv[i] = __halves2half2(__float2half_rn(t[k8 + 2 * i][n]), __float2half_rn(t[k8 + 2 * i + 1][n]));
    const long o = (long)(nb + n) * K + kt + k8;
    *(uint4*)(dh + o) = make_uint4(*(uint32_t*)&hv[0], *(uint32_t*)&hv[1],
                                   *(uint32_t*)&hv[2], *(uint32_t*)&hv[3]);
}

__global__ void tconv(const float* __restrict__ src, __half* __restrict__ dh, int K, int N)
{
    __shared__ float t[64][33];
    const int kt = blockIdx.y * 64, nb = blockIdx.x * 32;
    const int tid = threadIdx.x;
    {
        const int c4 = (tid & 7) * 4, r0 = tid >> 3;
#pragma unroll
        for (int p = 0; p < 2; p++) {
            const int r = r0 + p * 32;
            const float4 f = *(const float4*)(src + (size_t)(kt + r) * N + nb + c4);
            t[r][c4] = f.x; t[r][c4 + 1] = f.y; t[r][c4 + 2] = f.z; t[r][c4 + 3] = f.w;
        }
    }
    __syncthreads();
    const int n  = tid >> 3;
    const int k8 = (tid & 7) * 8;
    __half2 hv[4];
#pragma unroll
    for (int i = 0; i < 4; i++)
        hv[i] = __halves2half2(__float2half_rn(t[k8 + 2 * i][n]), __float2half_rn(t[k8 + 2 * i + 1][n]));
    const long o = (long)(nb + n) * K + kt + k8;
    *(uint4*)(dh + o) = make_uint4(*(uint32_t*)&hv[0], *(uint32_t*)&hv[1],
                                   *(uint32_t*)&hv[2], *(uint32_t*)&hv[3]);
}

// ---------------- LayerNorm kernels ----------------
__global__ void ln_newh(const float* __restrict__ u, const float* __restrict__ h,
                        const float* __restrict__ g, const float* __restrict__ up,
                        const float* __restrict__ gamma, const float* __restrict__ beta,
                        float* __restrict__ out, __half* __restrict__ a3)
{
    const int row = blockIdx.x, tid = threadIdx.x;
    const int PER = H_ / 256;
    const long base = (long)row * H_;
    float v[PER];
    float s = 0.f, ss = 0.f;
#pragma unroll
    for (int i = 0; i < PER; i++) {
        const int j = i * 256 + tid;
        const float uu = u[base + j];
        const float gg = g[base + j];
        const float val = h[base + j] * (2.f - uu) + uu * (gg * sigm(gg)) * up[base + j];
        v[i] = val; s += val; ss += val * val;
    }
    __shared__ float sm[2][8];
#pragma unroll
    for (int o = 16; o > 0; o >>= 1) {
        s  += __shfl_xor_sync(0xffffffffu, s, o);
        ss += __shfl_xor_sync(0xffffffffu, ss, o);
    }
    const int warp = tid >> 5, lane = tid & 31;
    if (lane == 0) { sm[0][warp] = s; sm[1][warp] = ss; }
    __syncthreads();
    float ts = 0.f, tss = 0.f;
#pragma unroll
    for (int w = 0; w < 8; w++) { ts += sm[0][w]; tss += sm[1][w]; }
    const float mean = ts / (float)H_;
    const float var  = tss / (float)H_ - mean * mean;
    const float rstd = rsqrtf(var + LN_EPS);
#pragma unroll
    for (int i = 0; i < PER; i++) {
        const int j = i * 256 + tid;
        const float r = (v[i] - mean) * rstd * gamma[j] + beta[j];
        out[base + j] = r;
        a3[base + j] = __float2half_rn(r);
    }
}

__global__ void ln_out(const float* __restrict__ in,
                       const float* __restrict__ bd,
                       const float* __restrict__ gamma, const float* __restrict__ beta,
                       float* __restrict__ out)
{
    const int row = blockIdx.x, tid = threadIdx.x;
    const int PER = D_ / 256;
    const long base = (long)row * D_;
    const long zoff = (long)B_ * D_;
    float v[PER];
    float s = 0.f, ss = 0.f;
#pragma unroll
    for (int i = 0; i < PER; i++) {
        const int j = i * 256 + tid;
        float val = bd[j];
#pragma unroll
        for (int z = 0; z < KSLICE_D; z++) val += in[z * zoff + base + j];
        v[i] = val; s += val; ss += val * val;
    }
    __shared__ float sm[2][8];
#pragma unroll
    for (int o = 16; o > 0; o >>= 1) {
        s  += __shfl_xor_sync(0xffffffffu, s, o);
        ss += __shfl_xor_sync(0xffffffffu, ss, o);
    }
    const int warp = tid >> 5, lane = tid & 31;
    if (lane == 0) { sm[0][warp] = s; sm[1][warp] = ss; }
    __syncthreads();
    float ts = 0.f, tss = 0.f;
#pragma unroll
    for (int w = 0; w < 8; w++) { ts += sm[0][w]; tss += sm[1][w]; }
    const float mean = ts / (float)D_;
    const float var  = tss / (float)D_ - mean * mean;
    const float rstd = rsqrtf(var + LN_EPS);
#pragma unroll
    for (int i = 0; i < PER; i++) {
        const int j = i * 256 + tid;
        out[base + j] = (v[i] - mean) * rstd * gamma[j] + beta[j];
    }
}

// ---------------- host ----------------
extern "C" void kernel_launch(void* const* d_in, const int* in_sizes, int n_in,
                              void* d_out, int out_size)
{
    const float* x    = (const float*)d_in[0];
    const float* h    = (const float*)d_in[1];
    const float* W_u  = (const float*)d_in[2];
    const float* b_u  = (const float*)d_in[3];
    const float* W_r  = (const float*)d_in[4];
    const float* b_r  = (const float*)d_in[5];
    const float* W_g  = (const float*)d_in[6];
    const float* b_g  = (const float*)d_in[7];
    const float* W_up = (const float*)d_in[8];
    const float* b_up = (const float*)d_in[9];
    const float* W_d  = (const float*)d_in[10];
    const float* b_d  = (const float*)d_in[11];
    const float* g_hh = (const float*)d_in[12];
    const float* be_h = (const float*)d_in[13];
    const float* g_o  = (const float*)d_in[14];
    const float* be_o = (const float*)d_in[15];
    float* out = (float*)d_out;

    void *pa1, *pa2, *pa3, *pwu, *pwr, *pwg, *pwp, *pwd;
    float *pu, *pg, *pup, *pnh, *pdo;
    cudaGetSymbolAddress(&pa1, g_a1);
    cudaGetSymbolAddress(&pa2, g_a2);
    cudaGetSymbolAddress(&pa3, g_a3);
    cudaGetSymbolAddress(&pwu, g_wu); cudaGetSymbolAddress(&pwr, g_wr);
    cudaGetSymbolAddress(&pwg, g_wg); cudaGetSymbolAddress(&pwp, g_wp);
    cudaGetSymbolAddress(&pwd, g_wd);
    cudaGetSymbolAddress((void**)&pu,  g_u);
    cudaGetSymbolAddress((void**)&pg,  g_g);
    cudaGetSymbolAddress((void**)&pup, g_up);
    cudaGetSymbolAddress((void**)&pnh, g_nh);
    cudaGetSymbolAddress((void**)&pdo, g_do);

    constexpr int SMEM = STG * (int)STAGE_BYTES;  // 73728, 1 CTA/SM
    cudaFuncSetAttribute((const void*)gemm_hmma<0>, cudaFuncAttributeMaxDynamicSharedMemorySize, SMEM);
    cudaFuncSetAttribute((const void*)gemm_hmma<1>, cudaFuncAttributeMaxDynamicSharedMemorySize, SMEM);
    cudaFuncSetAttribute((const void*)gemm_hmma<2>, cudaFuncAttributeMaxDynamicSharedMemorySize, SMEM);

    float* newh = (out_size >= B_ * (D_ + H_)) ? (out + (long)B_ * D_) : pnh;

    conv_a1<<<(unsigned)(((long)B_ * C_ / 4 + 255) / 256), 256>>>(
        x, h, (__half*)pa1, (__half*)pa2);

    tconv4<<<dim3(H_ / 32, C_ / 64, 4), 256>>>(
        W_u, W_r, W_g, W_up,
        (__half*)pwu, (__half*)pwr, (__half*)pwg, (__half*)pwp);
    tconv<<<dim3(D_ / 32, H_ / 64), 256>>>(W_d, (__half*)pwd, H_, D_);

    // u = sigmoid([x|h]Wu+bu);  rh = sigmoid([x|h]Wr+br)*h -> fp16 into A2
    gemm_hmma<0><<<dim3(32, 8, 1), 256, SMEM>>>(
        (const __half*)pa1, C_,
        (const __half*)pwu, (const __half*)pwr, C_,
        b_u, b_r, h, pu, nullptr,
        (__half*)pa2, C_, 16, 1);

    // g = [x|rh]Wg+bg ; up = [x|rh]Wup+bup (raw f32)
    gemm_hmma<1><<<dim3(32, 8, 1), 256, SMEM>>>(
        (const __half*)pa2, C_,
        (const __half*)pwg, (const __half*)pwp, C_,
        b_g, b_up, nullptr, pg, pup, nullptr, C_, 16, 1);

    ln_newh<<<B_, 256>>>(pu, h, pg, pup, g_hh, be_h, newh, (__half*)pa3);

    // down: new_h @ W_d (split-K x4, raw partials)
    gemm_hmma<2><<<dim3(4, 8, KSLICE_D), 256, SMEM>>>(
        (const __half*)pa3, H_,
        (const __half*)pwd, (const __half*)pwd, H_,
        b_d, b_d, nullptr, pdo, nullptr, nullptr, H_, 1000, KSLICE_D);

    ln_out<<<B_, 256>>>(pdo, b_d, g_o, be_o, out);
}

// round 13
// speedup vs baseline: 1.1861x; 1.1861x over previous
#include <cuda_runtime.h>
#include <cuda_fp16.h>
#include <math.h>
#include <stdint.h>

#define B_ 1024
#define D_ 1024
#define H_ 4096
#define C_ 5120
#define LN_EPS 1e-3f
#define KSLICE_D 4

// ---------------- scratch (device globals: allocation-free) ----------------
__device__ __align__(1024) __half g_a1[B_ * C_];
__device__ __align__(1024) __half g_a2[B_ * C_];
__device__ __align__(1024) __half g_a3[B_ * H_];
__device__ __align__(1024) __half g_wu[(long)H_ * C_];
__device__ __align__(1024) __half g_wr[(long)H_ * C_];
__device__ __align__(1024) __half g_wg[(long)H_ * C_];
__device__ __align__(1024) __half g_wp[(long)H_ * C_];
__device__ __align__(1024) __half g_wd[(long)D_ * H_];
__device__ float g_u [B_ * H_];
__device__ float g_g [B_ * H_];
__device__ float g_up[B_ * H_];
__device__ float g_nh[B_ * H_];
__device__ float g_do[KSLICE_D * B_ * D_];

// ---------------- helpers ----------------
__device__ __forceinline__ uint32_t smem_u32(const void* p) {
    uint32_t a;
    asm("{ .reg .u64 t; cvta.to.shared.u64 t, %1; cvt.u32.u64 %0, t; }" : "=r"(a) : "l"(p));
    return a;
}
__device__ __forceinline__ void cp16(uint32_t dst, const void* src) {
    asm volatile("cp.async.cg.shared.global [%0], [%1], 16;" :: "r"(dst), "l"(src) : "memory");
}
__device__ __forceinline__ void ldsm_x4(uint32_t* r, uint32_t addr) {
    asm volatile("ldmatrix.sync.aligned.m8n8.x4.shared.b16 {%0,%1,%2,%3}, [%4];"
                 : "=r"(r[0]), "=r"(r[1]), "=r"(r[2]), "=r"(r[3]) : "r"(addr));
}
__device__ __forceinline__ void mma_f32(float* c, const uint32_t* a, uint32_t b0, uint32_t b1) {
    asm volatile(
        "mma.sync.aligned.m16n8k16.row.col.f32.f16.f16.f32 "
        "{%0,%1,%2,%3}, {%4,%5,%6,%7}, {%8,%9}, {%0,%1,%2,%3};"
        : "+f"(c[0]), "+f"(c[1]), "+f"(c[2]), "+f"(c[3])
        : "r"(a[0]), "r"(a[1]), "r"(a[2]), "r"(a[3]), "r"(b0), "r"(b1));
}
__device__ __forceinline__ float sigm(float x) { return 1.0f / (1.0f + expf(-x)); }

// 128B-row swizzle (R4/R6-proven): tile [128 rows][64 fp16], 8 chunks of 16B per row
__device__ __forceinline__ uint32_t sw128(int row, int cb) {
    return (uint32_t)row * 128u + (uint32_t)((cb ^ (row & 7)) << 4);
}

// ---------------- single-term fp16 HMMA GEMM (64x32 warp tiles, 2 CTAs/SM, KT=64) ----------------
#define KT 64
#define STG 3
#define STAGE_BYTES 32768u   // A(0): 128x64 fp16 = 16KB; B(16384): 128x64 fp16 = 16KB

template<int MODE>
__global__ void __launch_bounds__(256, 2) gemm_hmma(
    const __half* __restrict__ A, int ldA,
    const __half* __restrict__ B0, const __half* __restrict__ B1, int ldB,
    const float* __restrict__ bias0, const float* __restrict__ bias1,
    const float* __restrict__ hmul,
    float* __restrict__ fout0, float* __restrict__ fout1,
    __half* __restrict__ oba,
    int K, int nhalf, int kslices)
{
    extern __shared__ __align__(1024) char smraw[];
    const uint32_t sb = smem_u32(smraw);

    const int tid = threadIdx.x, lane = tid & 31, wid = tid >> 5;
    const int wm = (wid >> 2) * 64;   // warp M offset (0/64)
    const int wn = (wid & 3) * 32;    // warp N offset (0/32/64/96)
    const int nt = blockIdx.x, mt = blockIdx.y;
    const bool second = nt >= nhalf;
    const int ntin = second ? nt - nhalf : nt;
    const __half* Bp = second ? B1 : B0;
    const float* bias = second ? bias1 : bias0;

    const int m0 = mt * 128, n0 = ntin * 128;
    const int Ks = K / kslices;
    const int kbeg = blockIdx.z * Ks;
    const int S = Ks / KT;

    // ---- stage loader: A+B each 128x64 fp16, 4+4 cp16/thread ----
    const int lr  = tid >> 1;            // row 0..127
    const int lcb = (tid & 1) * 4;       // chunk base 0 or 4
    auto load_stage = [&](int slot, int kk) {
        const uint32_t tb = sb + (uint32_t)slot * STAGE_BYTES;
        const size_t arow = (size_t)(m0 + lr) * ldA + kk;
        const size_t brow = (size_t)(n0 + lr) * ldB + kk;
#pragma unroll
        for (int c = 0; c < 4; c++) {
            const int cb = lcb + c;
            const uint32_t sw = sw128(lr, cb);
            cp16(tb + sw,          A  + arow + cb * 8);
            cp16(tb + 16384 + sw,  Bp + brow + cb * 8);
        }
    };

    // ldsm geometry: row fixed per thread; chunk = 2*s + lb varies per k-step
    const int lb = (lane >> 4) & 1;
    uint32_t rbA[4], rbB[2];
    int r7A[4], r7B[2];
#pragma unroll
    for (int i = 0; i < 4; i++) {
        const int row = wm + i * 16 + (lane & 15);
        rbA[i] = (uint32_t)row * 128u;
        r7A[i] = row & 7;
    }
#pragma unroll
    for (int jp = 0; jp < 2; jp++) {
        const int row = wn + jp * 16 + (lane & 15);
        rbB[jp] = (uint32_t)row * 128u;
        r7B[jp] = row & 7;
    }

    // prologue
#pragma unroll
    for (int s = 0; s < STG - 1; s++) {
        if (s < S) load_stage(s, kbeg + s * KT);
        asm volatile("cp.async.commit_group;" ::: "memory");
    }

    float acc[4][4][4];
#pragma unroll
    for (int i = 0; i < 4; i++)
#pragma unroll
        for (int j = 0; j < 4; j++)
#pragma unroll
            for (int e = 0; e < 4; e++) acc[i][j][e] = 0.f;

    for (int ks = 0; ks < S; ks++) {
        asm volatile("cp.async.wait_group 1;" ::: "memory");
        __syncthreads();
        if (ks + STG - 1 < S) load_stage((ks + STG - 1) % STG, kbeg + (ks + STG - 1) * KT);
        asm volatile("cp.async.commit_group;" ::: "memory");

        const uint32_t base = sb + (uint32_t)(ks % STG) * STAGE_BYTES;
#pragma unroll
        for (int s = 0; s < 4; s++) {   // 4 k16 steps per 64-K stage
            const int cb = 2 * s + lb;
            uint32_t a[4][4], b[2][4];
#pragma unroll
            for (int i = 0; i < 4; i++)
                ldsm_x4(a[i], base + rbA[i] + (uint32_t)((cb ^ r7A[i]) << 4));
#pragma unroll
            for (int jp = 0; jp < 2; jp++)
                ldsm_x4(b[jp], base + 16384 + rbB[jp] + (uint32_t)((cb ^ r7B[jp]) << 4));
#pragma unroll
            for (int i = 0; i < 4; i++)
#pragma unroll
                for (int j = 0; j < 4; j++)
                    mma_f32(acc[i][j], a[i], b[j >> 1][j & 1], b[j >> 1][2 | (j & 1)]);
        }
    }

    // ---- epilogue ----
#pragma unroll
    for (int i = 0; i < 4; i++) {
#pragma unroll
        for (int j = 0; j < 4; j++) {
            const int r0 = m0 + wm + i * 16 + (lane >> 2);
            const int gc = ntin * 128 + wn + j * 8 + 2 * (lane & 3);
#pragma unroll
            for (int half = 0; half < 2; half++) {
                const int row = r0 + half * 8;
                const float v0r = acc[i][j][half * 2];
                const float v1r = acc[i][j][half * 2 + 1];
                if (MODE == 0) {
                    const float v0 = v0r + bias[gc], v1 = v1r + bias[gc + 1];
                    if (!second) {
                        fout0[(long)row * H_ + gc]     = sigm(v0);
                        fout0[(long)row * H_ + gc + 1] = sigm(v1);
                    } else {
                        const float rh0 = sigm(v0) * hmul[(long)row * H_ + gc];
                        const float rh1 = sigm(v1) * hmul[(long)row * H_ + gc + 1];
                        oba[(long)row * C_ + D_ + gc]     = __float2half_rn(rh0);
                        oba[(long)row * C_ + D_ + gc + 1] = __float2half_rn(rh1);
                    }
                } else if (MODE == 1) {
                    float* dst = second ? fout1 : fout0;
                    dst[(long)row * H_ + gc]     = v0r + bias[gc];
                    dst[(long)row * H_ + gc + 1] = v1r + bias[gc + 1];
                } else {
                    float* dst = fout0 + (size_t)blockIdx.z * B_ * D_;
                    dst[(long)row * D_ + gc]     = v0r;
                    dst[(long)row * D_ + gc + 1] = v1r;
                }
            }
        }
    }
}

// ---------------- conversion kernels ----------------
__global__ void conv_a1(const float* __restrict__ x, const float* __restrict__ h,
                        __half* __restrict__ a1, __half* __restrict__ a2)
{
    const long i4 = (long)blockIdx.x * blockDim.x + threadIdx.x;
    if (i4 >= (long)B_ * C_ / 4) return;
    const int row = (int)(i4 / (C_ / 4));
    const int c = (int)(i4 % (C_ / 4)) * 4;
    float4 f;
    if (c < D_) f = *(const float4*)(x + (long)row * D_ + c);
    else        f = *(const float4*)(h + (long)row * H_ + (c - D_));
    __half2 hv0 = __halves2half2(__float2half_rn(f.x), __float2half_rn(f.y));
    __half2 hv1 = __halves2half2(__float2half_rn(f.z), __float2half_rn(f.w));
    const long o = (long)row * C_ + c;
    *(uint2*)(a1 + o) = make_uint2(*(uint32_t*)&hv0, *(uint32_t*)&hv1);
    if (c < D_)
        *(uint2*)(a2 + o) = make_uint2(*(uint32_t*)&hv0, *(uint32_t*)&hv1);
}

// batched transpose + round to fp16 for the 4 big weights
__global__ void tconv4(const float* __restrict__ s0, const float* __restrict__ s1,
                       const float* __restrict__ s2, const float* __restrict__ s3,
                       __half* __restrict__ d0, __half* __restrict__ d1,
                       __half* __restrict__ d2, __half* __restrict__ d3)
{
    const int z = blockIdx.z;
    const float* src = z == 0 ? s0 : z == 1 ? s1 : z == 2 ? s2 : s3;
    __half* dh = z == 0 ? d0 : z == 1 ? d1 : z == 2 ? d2 : d3;
    const int K = C_, N = H_;

    __shared__ float t[64][33];
    const int kt = blockIdx.y * 64, nb = blockIdx.x * 32;
    const int tid = threadIdx.x;
    {
        const int c4 = (tid & 7) * 4, r0 = tid >> 3;
#pragma unroll
        for (int p = 0; p < 2; p++) {
            const int r = r0 + p * 32;
            const float4 f = *(const float4*)(src + (size_t)(kt + r) * N + nb + c4);
            t[r][c4] = f.x; t[r][c4 + 1] = f.y; t[r][c4 + 2] = f.z; t[r][c4 + 3] = f.w;
        }
    }
    __syncthreads();
    const int n  = tid >> 3;
    const int k8 = (tid & 7) * 8;
    __half2 hv[4];
#pragma unroll
    for (int i = 0; i < 4; i++)
        hv[i] = __halves2half2(__float2half_rn(t[k8 + 2 * i][n]), __float2half_rn(t[k8 + 2 * i + 1][n]));
    const long o = (long)(nb + n) * K + kt + k8;
    *(uint4*)(dh + o) = make_uint4(*(uint32_t*)&hv[0], *(uint32_t*)&hv[1],
                                   *(uint32_t*)&hv[2], *(uint32_t*)&hv[3]);
}

__global__ void tconv(const float* __restrict__ src, __half* __restrict__ dh, int K, int N)
{
    __shared__ float t[64][33];
    const int kt = blockIdx.y * 64, nb = blockIdx.x * 32;
    const int tid = threadIdx.x;
    {
        const int c4 = (tid & 7) * 4, r0 = tid >> 3;
#pragma unroll
        for (int p = 0; p < 2; p++) {
            const int r = r0 + p * 32;
            const float4 f = *(const float4*)(src + (size_t)(kt + r) * N + nb + c4);
            t[r][c4] = f.x; t[r][c4 + 1] = f.y; t[r][c4 + 2] = f.z; t[r][c4 + 3] = f.w;
        }
    }
    __syncthreads();
    const int n  = tid >> 3;
    const int k8 = (tid & 7) * 8;
    __half2 hv[4];
#pragma unroll
    for (int i = 0; i < 4; i++)
        hv[i] = __halves2half2(__float2half_rn(t[k8 + 2 * i][n]), __float2half_rn(t[k8 + 2 * i + 1][n]));
    const long o = (long)(nb + n) * K + kt + k8;
    *(uint4*)(dh + o) = make_uint4(*(uint32_t*)&hv[0], *(uint32_t*)&hv[1],
                                   *(uint32_t*)&hv[2], *(uint32_t*)&hv[3]);
}

// ---------------- LayerNorm kernels ----------------
__global__ void ln_newh(const float* __restrict__ u, const float* __restrict__ h,
                        const float* __restrict__ g, const float* __restrict__ up,
                        const float* __restrict__ gamma, const float* __restrict__ beta,
                        float* __restrict__ out, __half* __restrict__ a3)
{
    const int row = blockIdx.x, tid = threadIdx.x;
    const int PER = H_ / 256;
    const long base = (long)row * H_;
    float v[PER];
    float s = 0.f, ss = 0.f;
#pragma unroll
    for (int i = 0; i < PER; i++) {
        const int j = i * 256 + tid;
        const float uu = u[base + j];
        const float gg = g[base + j];
        const float val = h[base + j] * (2.f - uu) + uu * (gg * sigm(gg)) * up[base + j];
        v[i] = val; s += val; ss += val * val;
    }
    __shared__ float sm[2][8];
#pragma unroll
    for (int o = 16; o > 0; o >>= 1) {
        s  += __shfl_xor_sync(0xffffffffu, s, o);
        ss += __shfl_xor_sync(0xffffffffu, ss, o);
    }
    const int warp = tid >> 5, lane = tid & 31;
    if (lane == 0) { sm[0][warp] = s; sm[1][warp] = ss; }
    __syncthreads();
    float ts = 0.f, tss = 0.f;
#pragma unroll
    for (int w = 0; w < 8; w++) { ts += sm[0][w]; tss += sm[1][w]; }
    const float mean = ts / (float)H_;
    const float var  = tss / (float)H_ - mean * mean;
    const float rstd = rsqrtf(var + LN_EPS);
#pragma unroll
    for (int i = 0; i < PER; i++) {
        const int j = i * 256 + tid;
        const float r = (v[i] - mean) * rstd * gamma[j] + beta[j];
        out[base + j] = r;
        a3[base + j] = __float2half_rn(r);
    }
}

__global__ void ln_out(const float* __restrict__ in,
                       const float* __restrict__ bd,
                       const float* __restrict__ gamma, const float* __restrict__ beta,
                       float* __restrict__ out)
{
    const int row = blockIdx.x, tid = threadIdx.x;
    const int PER = D_ / 256;
    const long base = (long)row * D_;
    const long zoff = (long)B_ * D_;
    float v[PER];
    float s = 0.f, ss = 0.f;
#pragma unroll
    for (int i = 0; i < PER; i++) {
        const int j = i * 256 + tid;
        float val = bd[j];
#pragma unroll
        for (int z = 0; z < KSLICE_D; z++) val += in[z * zoff + base + j];
        v[i] = val; s += val; ss += val * val;
    }
    __shared__ float sm[2][8];
#pragma unroll
    for (int o = 16; o > 0; o >>= 1) {
        s  += __shfl_xor_sync(0xffffffffu, s, o);
        ss += __shfl_xor_sync(0xffffffffu, ss, o);
    }
    const int warp = tid >> 5, lane = tid & 31;
    if (lane == 0) { sm[0][warp] = s; sm[1][warp] = ss; }
    __syncthreads();
    float ts = 0.f, tss = 0.f;
#pragma unroll
    for (int w = 0; w < 8; w++) { ts += sm[0][w]; tss += sm[1][w]; }
    const float mean = ts / (float)D_;
    const float var  = tss / (float)D_ - mean * mean;
    const float rstd = rsqrtf(var + LN_EPS);
#pragma unroll
    for (int i = 0; i < PER; i++) {
        const int j = i * 256 + tid;
        out[base + j] = (v[i] - mean) * rstd * gamma[j] + beta[j];
    }
}

// ---------------- host ----------------
extern "C" void kernel_launch(void* const* d_in, const int* in_sizes, int n_in,
                              void* d_out, int out_size)
{
    const float* x    = (const float*)d_in[0];
    const float* h    = (const float*)d_in[1];
    const float* W_u  = (const float*)d_in[2];
    const float* b_u  = (const float*)d_in[3];
    const float* W_r  = (const float*)d_in[4];
    const float* b_r  = (const float*)d_in[5];
    const float* W_g  = (const float*)d_in[6];
    const float* b_g  = (const float*)d_in[7];
    const float* W_up = (const float*)d_in[8];
    const float* b_up = (const float*)d_in[9];
    const float* W_d  = (const float*)d_in[10];
    const float* b_d  = (const float*)d_in[11];
    const float* g_hh = (const float*)d_in[12];
    const float* be_h = (const float*)d_in[13];
    const float* g_o  = (const float*)d_in[14];
    const float* be_o = (const float*)d_in[15];
    float* out = (float*)d_out;

    void *pa1, *pa2, *pa3, *pwu, *pwr, *pwg, *pwp, *pwd;
    float *pu, *pg, *pup, *pnh, *pdo;
    cudaGetSymbolAddress(&pa1, g_a1);
    cudaGetSymbolAddress(&pa2, g_a2);
    cudaGetSymbolAddress(&pa3, g_a3);
    cudaGetSymbolAddress(&pwu, g_wu); cudaGetSymbolAddress(&pwr, g_wr);
    cudaGetSymbolAddress(&pwg, g_wg); cudaGetSymbolAddress(&pwp, g_wp);
    cudaGetSymbolAddress(&pwd, g_wd);
    cudaGetSymbolAddress((void**)&pu,  g_u);
    cudaGetSymbolAddress((void**)&pg,  g_g);
    cudaGetSymbolAddress((void**)&pup, g_up);
    cudaGetSymbolAddress((void**)&pnh, g_nh);
    cudaGetSymbolAddress((void**)&pdo, g_do);

    constexpr int SMEM = STG * (int)STAGE_BYTES;  // 98304 -> 2 CTAs/SM
    cudaFuncSetAttribute((const void*)gemm_hmma<0>, cudaFuncAttributeMaxDynamicSharedMemorySize, SMEM);
    cudaFuncSetAttribute((const void*)gemm_hmma<1>, cudaFuncAttributeMaxDynamicSharedMemorySize, SMEM);
    cudaFuncSetAttribute((const void*)gemm_hmma<2>, cudaFuncAttributeMaxDynamicSharedMemorySize, SMEM);

    float* newh = (out_size >= B_ * (D_ + H_)) ? (out + (long)B_ * D_) : pnh;

    conv_a1<<<(unsigned)(((long)B_ * C_ / 4 + 255) / 256), 256>>>(
        x, h, (__half*)pa1, (__half*)pa2);

    tconv4<<<dim3(H_ / 32, C_ / 64, 4), 256>>>(
        W_u, W_r, W_g, W_up,
        (__half*)pwu, (__half*)pwr, (__half*)pwg, (__half*)pwp);
    tconv<<<dim3(D_ / 32, H_ / 64), 256>>>(W_d, (__half*)pwd, H_, D_);

    // u = sigmoid([x|h]Wu+bu);  rh = sigmoid([x|h]Wr+br)*h -> fp16 into A2
    gemm_hmma<0><<<dim3(64, 8, 1), 256, SMEM>>>(
        (const __half*)pa1, C_,
        (const __half*)pwu, (const __half*)pwr, C_,
        b_u, b_r, h, pu, nullptr,
        (__half*)pa2, C_, 32, 1);

    // g = [x|rh]Wg+bg ; up = [x|rh]Wup+bup (raw f32)
    gemm_hmma<1><<<dim3(64, 8, 1), 256, SMEM>>>(
        (const __half*)pa2, C_,
        (const __half*)pwg, (const __half*)pwp, C_,
        b_g, b_up, nullptr, pg, pup, nullptr, C_, 32, 1);

    ln_newh<<<B_, 256>>>(pu, h, pg, pup, g_hh, be_h, newh, (__half*)pa3);

    // down: new_h @ W_d (split-K x4, raw partials)
    gemm_hmma<2><<<dim3(8, 8, KSLICE_D), 256, SMEM>>>(
        (const __half*)pa3, H_,
        (const __half*)pwd, (const __half*)pwd, H_,
        b_d, b_d, nullptr, pdo, nullptr, nullptr, H_, 1000, KSLICE_D);

    ln_out<<<B_, 256>>>(pdo, b_d, g_o, be_o, out);
}

// round 14
// speedup vs baseline: 1.2657x; 1.0672x over previous
#include <cuda_runtime.h>
#include <cuda_fp16.h>
#include <math.h>
#include <stdint.h>

#define B_ 1024
#define D_ 1024
#define H_ 4096
#define C_ 5120
#define LN_EPS 1e-3f
#define KSLICE_D 4

// ---------------- scratch (device globals: allocation-free) ----------------
__device__ __align__(1024) __half g_a1[B_ * C_];
__device__ __align__(1024) __half g_a2[B_ * C_];
__device__ __align__(1024) __half g_a3[B_ * H_];
__device__ __align__(1024) __half g_wu[(long)H_ * C_];
__device__ __align__(1024) __half g_wr[(long)H_ * C_];
__device__ __align__(1024) __half g_wg[(long)H_ * C_];
__device__ __align__(1024) __half g_wp[(long)H_ * C_];
__device__ __align__(1024) __half g_wd[(long)D_ * H_];
__device__ float g_u [B_ * H_];
__device__ float g_g [B_ * H_];
__device__ float g_up[B_ * H_];
__device__ float g_nh[B_ * H_];
__device__ float g_do[KSLICE_D * B_ * D_];

// ---------------- helpers ----------------
__device__ __forceinline__ uint32_t smem_u32(const void* p) {
    uint32_t a;
    asm("{ .reg .u64 t; cvta.to.shared.u64 t, %1; cvt.u32.u64 %0, t; }" : "=r"(a) : "l"(p));
    return a;
}
__device__ __forceinline__ void cp16(uint32_t dst, const void* src) {
    asm volatile("cp.async.cg.shared.global [%0], [%1], 16;" :: "r"(dst), "l"(src) : "memory");
}
__device__ __forceinline__ void ldsm_x4(uint32_t* r, uint32_t addr) {
    asm volatile("ldmatrix.sync.aligned.m8n8.x4.shared.b16 {%0,%1,%2,%3}, [%4];"
                 : "=r"(r[0]), "=r"(r[1]), "=r"(r[2]), "=r"(r[3]) : "r"(addr));
}
__device__ __forceinline__ void mma_f32(float* c, const uint32_t* a, uint32_t b0, uint32_t b1) {
    asm volatile(
        "mma.sync.aligned.m16n8k16.row.col.f32.f16.f16.f32 "
        "{%0,%1,%2,%3}, {%4,%5,%6,%7}, {%8,%9}, {%0,%1,%2,%3};"
        : "+f"(c[0]), "+f"(c[1]), "+f"(c[2]), "+f"(c[3])
        : "r"(a[0]), "r"(a[1]), "r"(a[2]), "r"(a[3]), "r"(b0), "r"(b1));
}
__device__ __forceinline__ float sigm(float x) { return 1.0f / (1.0f + expf(-x)); }

// swizzled offset inside a [rows][32 fp16] tile (64B rows, 16B chunks) — R11-proven
__device__ __forceinline__ uint32_t sw_off(int row, int cb) {
    return (uint32_t)row * 64u + (uint32_t)((cb ^ ((row >> 1) & 3)) << 4);
}

// ---------------- shared tconv body (transpose + fp16 round, 64K x 32N tile) ----------------
// src [kdim, ndim] f32 -> dst [ndim, kdim] fp16. smem: float[64][33] (8448 B).
__device__ __forceinline__ void tconv_body(const float* __restrict__ src,
                                           __half* __restrict__ dst,
                                           int kdim, int ndim, int idx, void* smem)
{
    float (*t)[33] = reinterpret_cast<float(*)[33]>(smem);
    const int nblk = ndim / 32;
    const int nb = (idx % nblk) * 32;
    const int kt = (idx / nblk) * 64;
    const int tid = threadIdx.x;
    const int c4 = (tid & 7) * 4, r0 = tid >> 3;
#pragma unroll
    for (int p = 0; p < 2; p++) {
        const int r = r0 + p * 32;
        const float4 f = *(const float4*)(src + (size_t)(kt + r) * ndim + nb + c4);
        t[r][c4] = f.x; t[r][c4 + 1] = f.y; t[r][c4 + 2] = f.z; t[r][c4 + 3] = f.w;
    }
    __syncthreads();
    const int n  = tid >> 3;
    const int k8 = (tid & 7) * 8;
    __half2 hv[4];
#pragma unroll
    for (int i = 0; i < 4; i++)
        hv[i] = __halves2half2(__float2half_rn(t[k8 + 2 * i][n]), __float2half_rn(t[k8 + 2 * i + 1][n]));
    const long o = (long)(nb + n) * kdim + kt + k8;
    *(uint4*)(dst + o) = make_uint4(*(uint32_t*)&hv[0], *(uint32_t*)&hv[1],
                                    *(uint32_t*)&hv[2], *(uint32_t*)&hv[3]);
}

// ---------------- single-term fp16 HMMA GEMM + piggyback tconv (R11 geometry) ----------------
#define KT 32
#define STG 3
#define STAGE_BYTES 16384u   // A(0) B(8192), each 128x32 fp16 = 8KB

// Flattened 1D grid: [0, gb) gemm blocks, [gb, gb+tTotal) tconv blocks.
template<int MODE>
__global__ void __launch_bounds__(256, 2) gemm_fused(
    const __half* __restrict__ A, int ldA,
    const __half* __restrict__ B0, const __half* __restrict__ B1, int ldB,
    const float* __restrict__ bias0, const float* __restrict__ bias1,
    const float* __restrict__ hmul,
    float* __restrict__ fout0, float* __restrict__ fout1,
    __half* __restrict__ oba,
    int K, int ntx, int mty, int nhalf, int kslices,
    const float* __restrict__ ts0, const float* __restrict__ ts1,
    __half* __restrict__ td0, __half* __restrict__ td1,
    int tkdim, int tndim, int tPerW)
{
    extern __shared__ __align__(1024) char smraw[];
    const int gb = ntx * mty * kslices;
    const int bx = blockIdx.x;

    if (bx >= gb) {
        // ---- piggyback tconv block ----
        int idx = bx - gb;
        const float* src = ts0;
        __half* dst = td0;
        if (idx >= tPerW) { src = ts1; dst = td1; idx -= tPerW; }
        tconv_body(src, dst, tkdim, tndim, idx, smraw);
        return;
    }

    const uint32_t sb = smem_u32(smraw);
    const int tid = threadIdx.x, lane = tid & 31, wid = tid >> 5;
    const int wm = (wid >> 2) * 64;
    const int wn = (wid & 3) * 32;

    const int nt = bx % ntx;
    const int mt = (bx / ntx) % mty;
    const int kz = bx / (ntx * mty);
    const bool second = nt >= nhalf;
    const int ntin = second ? nt - nhalf : nt;
    const __half* Bp = second ? B1 : B0;
    const float* bias = second ? bias1 : bias0;

    const int m0 = mt * 128, n0 = ntin * 128;
    const int Ks = K / kslices;
    const int kbeg = kz * Ks;
    const int S = Ks / KT;

    // ---- stage loader ----
    const int lr  = tid >> 1;
    const int lcb = (tid & 1) * 2;
    auto load_stage = [&](int slot, int kk) {
        const uint32_t tb = sb + (uint32_t)slot * STAGE_BYTES;
        const size_t arow = (size_t)(m0 + lr) * ldA + kk;
        const size_t brow = (size_t)(n0 + lr) * ldB + kk;
#pragma unroll
        for (int c = 0; c < 2; c++) {
            const int cb = lcb + c;
            const uint32_t sw = tb + sw_off(lr, cb);
            cp16(sw,         A  + arow + cb * 8);
            cp16(sw + 8192,  Bp + brow + cb * 8);
        }
    };

    // precomputed ldsm offsets (s=0 chunk; s=1 toggles ^32)
    const int lb = (lane >> 4) & 1;
    uint32_t offA[4], offB[2];
#pragma unroll
    for (int i = 0; i < 4; i++) offA[i] = sw_off(wm + i * 16 + (lane & 15), lb);
#pragma unroll
    for (int jp = 0; jp < 2; jp++) offB[jp] = sw_off(wn + jp * 16 + (lane & 15), lb);

    // prologue
#pragma unroll
    for (int s = 0; s < STG - 1; s++) {
        if (s < S) load_stage(s, kbeg + s * KT);
        asm volatile("cp.async.commit_group;" ::: "memory");
    }

    float acc[4][4][4];
#pragma unroll
    for (int i = 0; i < 4; i++)
#pragma unroll
        for (int j = 0; j < 4; j++)
#pragma unroll
            for (int e = 0; e < 4; e++) acc[i][j][e] = 0.f;

    for (int ks = 0; ks < S; ks++) {
        asm volatile("cp.async.wait_group 1;" ::: "memory");
        __syncthreads();
        if (ks + STG - 1 < S) load_stage((ks + STG - 1) % STG, kbeg + (ks + STG - 1) * KT);
        asm volatile("cp.async.commit_group;" ::: "memory");

        const uint32_t base = sb + (uint32_t)(ks % STG) * STAGE_BYTES;
#pragma unroll
        for (int s = 0; s < 2; s++) {
            const uint32_t sx = (uint32_t)(s << 5);
            uint32_t a[4][4], b[2][4];
#pragma unroll
            for (int i = 0; i < 4; i++)   ldsm_x4(a[i], base + (offA[i] ^ sx));
#pragma unroll
            for (int jp = 0; jp < 2; jp++) ldsm_x4(b[jp], base + 8192 + (offB[jp] ^ sx));
#pragma unroll
            for (int i = 0; i < 4; i++)
#pragma unroll
                for (int j = 0; j < 4; j++)
                    mma_f32(acc[i][j], a[i], b[j >> 1][j & 1], b[j >> 1][2 | (j & 1)]);
        }
    }

    // ---- epilogue ----
#pragma unroll
    for (int i = 0; i < 4; i++) {
#pragma unroll
        for (int j = 0; j < 4; j++) {
            const int r0 = m0 + wm + i * 16 + (lane >> 2);
            const int gc = ntin * 128 + wn + j * 8 + 2 * (lane & 3);
#pragma unroll
            for (int half = 0; half < 2; half++) {
                const int row = r0 + half * 8;
                const float v0r = acc[i][j][half * 2];
                const float v1r = acc[i][j][half * 2 + 1];
                if (MODE == 0) {
                    const float v0 = v0r + bias[gc], v1 = v1r + bias[gc + 1];
                    if (!second) {
                        fout0[(long)row * H_ + gc]     = sigm(v0);
                        fout0[(long)row * H_ + gc + 1] = sigm(v1);
                    } else {
                        const float rh0 = sigm(v0) * hmul[(long)row * H_ + gc];
                        const float rh1 = sigm(v1) * hmul[(long)row * H_ + gc + 1];
                        oba[(long)row * C_ + D_ + gc]     = __float2half_rn(rh0);
                        oba[(long)row * C_ + D_ + gc + 1] = __float2half_rn(rh1);
                    }
                } else if (MODE == 1) {
                    float* dst = second ? fout1 : fout0;
                    dst[(long)row * H_ + gc]     = v0r + bias[gc];
                    dst[(long)row * H_ + gc + 1] = v1r + bias[gc + 1];
                } else {
                    float* dst = fout0 + (size_t)kz * B_ * D_;
                    dst[(long)row * D_ + gc]     = v0r;
                    dst[(long)row * D_ + gc + 1] = v1r;
                }
            }
        }
    }
}

// ---------------- prologue: conv_a1 blocks + tconv(W_u, W_r) blocks in one launch ----------------
#define CONV_BLOCKS (B_ * C_ / 4 / 256)   // 5120
#define TCONV_BIG   ((H_ / 32) * (C_ / 64))   // 10240 blocks per big weight

__global__ void __launch_bounds__(256, 2) prologue(
    const float* __restrict__ x, const float* __restrict__ h,
    __half* __restrict__ a1, __half* __restrict__ a2,
    const float* __restrict__ wu, const float* __restrict__ wr,
    __half* __restrict__ du, __half* __restrict__ dr)
{
    __shared__ float t[64][33];
    const int bx = blockIdx.x;
    if (bx < CONV_BLOCKS) {
        const long i4 = (long)bx * 256 + threadIdx.x;
        const int row = (int)(i4 / (C_ / 4));
        const int c = (int)(i4 % (C_ / 4)) * 4;
        float4 f;
        if (c < D_) f = *(const float4*)(x + (long)row * D_ + c);
        else        f = *(const float4*)(h + (long)row * H_ + (c - D_));
        __half2 hv0 = __halves2half2(__float2half_rn(f.x), __float2half_rn(f.y));
        __half2 hv1 = __halves2half2(__float2half_rn(f.z), __float2half_rn(f.w));
        const long o = (long)row * C_ + c;
        *(uint2*)(a1 + o) = make_uint2(*(uint32_t*)&hv0, *(uint32_t*)&hv1);
        if (c < D_)
            *(uint2*)(a2 + o) = make_uint2(*(uint32_t*)&hv0, *(uint32_t*)&hv1);
        return;
    }
    int idx = bx - CONV_BLOCKS;
    const float* src = wu;
    __half* dst = du;
    if (idx >= TCONV_BIG) { src = wr; dst = dr; idx -= TCONV_BIG; }
    tconv_body(src, dst, C_, H_, idx, t);
}

// ---------------- LayerNorm kernels ----------------
__global__ void ln_newh(const float* __restrict__ u, const float* __restrict__ h,
                        const float* __restrict__ g, const float* __restrict__ up,
                        const float* __restrict__ gamma, const float* __restrict__ beta,
                        float* __restrict__ out, __half* __restrict__ a3)
{
    const int row = blockIdx.x, tid = threadIdx.x;
    const int PER = H_ / 256;
    const long base = (long)row * H_;
    float v[PER];
    float s = 0.f, ss = 0.f;
#pragma unroll
    for (int i = 0; i < PER; i++) {
        const int j = i * 256 + tid;
        const float uu = u[base + j];
        const float gg = g[base + j];
        const float val = h[base + j] * (2.f - uu) + uu * (gg * sigm(gg)) * up[base + j];
        v[i] = val; s += val; ss += val * val;
    }
    __shared__ float sm[2][8];
#pragma unroll
    for (int o = 16; o > 0; o >>= 1) {
        s  += __shfl_xor_sync(0xffffffffu, s, o);
        ss += __shfl_xor_sync(0xffffffffu, ss, o);
    }
    const int warp = tid >> 5, lane = tid & 31;
    if (lane == 0) { sm[0][warp] = s; sm[1][warp] = ss; }
    __syncthreads();
    float ts = 0.f, tss = 0.f;
#pragma unroll
    for (int w = 0; w < 8; w++) { ts += sm[0][w]; tss += sm[1][w]; }
    const float mean = ts / (float)H_;
    const float var  = tss / (float)H_ - mean * mean;
    const float rstd = rsqrtf(var + LN_EPS);
#pragma unroll
    for (int i = 0; i < PER; i++) {
        const int j = i * 256 + tid;
        const float r = (v[i] - mean) * rstd * gamma[j] + beta[j];
        out[base + j] = r;
        a3[base + j] = __float2half_rn(r);
    }
}

__global__ void ln_out(const float* __restrict__ in,
                       const float* __restrict__ bd,
                       const float* __restrict__ gamma, const float* __restrict__ beta,
                       float* __restrict__ out)
{
    const int row = blockIdx.x, tid = threadIdx.x;
    const int PER = D_ / 256;
    const long base = (long)row * D_;
    const long zoff = (long)B_ * D_;
    float v[PER];
    float s = 0.f, ss = 0.f;
#pragma unroll
    for (int i = 0; i < PER; i++) {
        const int j = i * 256 + tid;
        float val = bd[j];
#pragma unroll
        for (int z = 0; z < KSLICE_D; z++) val += in[z * zoff + base + j];
        v[i] = val; s += val; ss += val * val;
    }
    __shared__ float sm[2][8];
#pragma unroll
    for (int o = 16; o > 0; o >>= 1) {
        s  += __shfl_xor_sync(0xffffffffu, s, o);
        ss += __shfl_xor_sync(0xffffffffu, ss, o);
    }
    const int warp = tid >> 5, lane = tid & 31;
    if (lane == 0) { sm[0][warp] = s; sm[1][warp] = ss; }
    __syncthreads();
    float ts = 0.f, tss = 0.f;
#pragma unroll
    for (int w = 0; w < 8; w++) { ts += sm[0][w]; tss += sm[1][w]; }
    const float mean = ts / (float)D_;
    const float var  = tss / (float)D_ - mean * mean;
    const float rstd = rsqrtf(var + LN_EPS);
#pragma unroll
    for (int i = 0; i < PER; i++) {
        const int j = i * 256 + tid;
        out[base + j] = (v[i] - mean) * rstd * gamma[j] + beta[j];
    }
}

// ---------------- host ----------------
extern "C" void kernel_launch(void* const* d_in, const int* in_sizes, int n_in,
                              void* d_out, int out_size)
{
    const float* x    = (const float*)d_in[0];
    const float* h    = (const float*)d_in[1];
    const float* W_u  = (const float*)d_in[2];
    const float* b_u  = (const float*)d_in[3];
    const float* W_r  = (const float*)d_in[4];
    const float* b_r  = (const float*)d_in[5];
    const float* W_g  = (const float*)d_in[6];
    const float* b_g  = (const float*)d_in[7];
    const float* W_up = (const float*)d_in[8];
    const float* b_up = (const float*)d_in[9];
    const float* W_d  = (const float*)d_in[10];
    const float* b_d  = (const float*)d_in[11];
    const float* g_hh = (const float*)d_in[12];
    const float* be_h = (const float*)d_in[13];
    const float* g_o  = (const float*)d_in[14];
    const float* be_o = (const float*)d_in[15];
    float* out = (float*)d_out;

    void *pa1, *pa2, *pa3, *pwu, *pwr, *pwg, *pwp, *pwd;
    float *pu, *pg, *pup, *pnh, *pdo;
    cudaGetSymbolAddress(&pa1, g_a1);
    cudaGetSymbolAddress(&pa2, g_a2);
    cudaGetSymbolAddress(&pa3, g_a3);
    cudaGetSymbolAddress(&pwu, g_wu); cudaGetSymbolAddress(&pwr, g_wr);
    cudaGetSymbolAddress(&pwg, g_wg); cudaGetSymbolAddress(&pwp, g_wp);
    cudaGetSymbolAddress(&pwd, g_wd);
    cudaGetSymbolAddress((void**)&pu,  g_u);
    cudaGetSymbolAddress((void**)&pg,  g_g);
    cudaGetSymbolAddress((void**)&pup, g_up);
    cudaGetSymbolAddress((void**)&pnh, g_nh);
    cudaGetSymbolAddress((void**)&pdo, g_do);

    constexpr int SMEM = STG * (int)STAGE_BYTES;  // 49152 -> 2 CTAs/SM
    cudaFuncSetAttribute((const void*)gemm_fused<0>, cudaFuncAttributeMaxDynamicSharedMemorySize, SMEM);
    cudaFuncSetAttribute((const void*)gemm_fused<1>, cudaFuncAttributeMaxDynamicSharedMemorySize, SMEM);
    cudaFuncSetAttribute((const void*)gemm_fused<2>, cudaFuncAttributeMaxDynamicSharedMemorySize, SMEM);

    float* newh = (out_size >= B_ * (D_ + H_)) ? (out + (long)B_ * D_) : pnh;

    // prologue: conv_a1 + tconv(W_u) + tconv(W_r), one launch
    prologue<<<CONV_BLOCKS + 2 * TCONV_BIG, 256>>>(
        x, h, (__half*)pa1, (__half*)pa2, W_u, W_r, (__half*)pwu, (__half*)pwr);

    // GEMM1 (u, rh) + hidden tconv(W_g, W_up)
    {
        const int gb = 64 * 8;  // ntx * mty
        gemm_fused<0><<<gb + 2 * TCONV_BIG, 256, SMEM>>>(
            (const __half*)pa1, C_,
            (const __half*)pwu, (const __half*)pwr, C_,
            b_u, b_r, h, pu, nullptr, (__half*)pa2,
            C_, 64, 8, 32, 1,
            W_g, W_up, (__half*)pwg, (__half*)pwp, C_, H_, TCONV_BIG);
    }

    // GEMM2 (g, up) + hidden tconv(W_d)
    {
        const int gb = 64 * 8;
        const int tWd = (D_ / 32) * (H_ / 64);  // 2048
        gemm_fused<1><<<gb + tWd, 256, SMEM>>>(
            (const __half*)pa2, C_,
            (const __half*)pwg, (const __half*)pwp, C_,
            b_g, b_up, nullptr, pg, pup, nullptr,
            C_, 64, 8, 32, 1,
            W_d, W_d, (__half*)pwd, (__half*)pwd, H_, D_, tWd);
    }

    ln_newh<<<B_, 256>>>(pu, h, pg, pup, g_hh, be_h, newh, (__half*)pa3);

    // down: new_h @ W_d (split-K x4)
    gemm_fused<2><<<8 * 8 * KSLICE_D, 256, SMEM>>>(
        (const __half*)pa3, H_,
        (const __half*)pwd, (const __half*)pwd, H_,
        b_d, b_d, nullptr, pdo, nullptr, nullptr,
        H_, 8, 8, 1000, KSLICE_D,
        nullptr, nullptr, nullptr, nullptr, 1, 32, 0);

    ln_out<<<B_, 256>>>(pdo, b_d, g_o, be_o, out);
}